// round 14
// baseline (speedup 1.0000x reference)
#include <cuda_runtime.h>
#include <cuda_bf16.h>
#include <cuda_fp16.h>
#include <math.h>
#include <cstdint>

#define N_PTS   524288
#define GRID_R  300
#define NCOMP   36
#define SDF_DIM 256
#define IN_CH   129
#define OUT_CH  129
#define TILE_M  128
#define N_TILES (N_PTS / TILE_M)      // 4096
#define N_UNITS (N_PTS / 64)          // 8192 64-row units

#define GTHREADS 256
#define MTHREADS 512                  // 16 warps = 2 groups x 8 warps

// ---- mlp kernel smem map (bytes) ----
#define W1S_OFF  0                    // 256 x 304B = 77824
#define W2S_OFF  77824                // 128 x 528B = 67584
#define HS_OFF   145408               // 2 groups x 64 x 528B = 67584 (stage overlays)
#define HS_GRP   33792                // per-group H bytes
#define LUT_OFF  212992               // 64 entries x 32 banks x 4B = 8192
#define W2C_OFF  221184               // 256 * 4
#define B2S_OFF  222208               // 132 * 4
#define C128_OFF 222736               // 2 grp x 4 x 64 x 4 = 2048
#define SMEM_B   224784

typedef unsigned int u32;

__device__ __half g_planesT[3*GRID_R*GRID_R*NCOMP];        // fp16: 19.4MB, L2-resident
__device__ float  g_linesT [3*GRID_R*NCOMP];
__device__ __align__(16) unsigned short g_w1bf[256*144];   // [n][k], k129=b1, 130..143=0
__device__ __align__(16) unsigned short g_w2bf[128*256];   // [n][k]
__device__ uint4 g_X[N_TILES*8*9*32];                      // A-fragments (16-row strips)

__device__ __forceinline__ u32 smem_u32(const void* p) {
    u32 a; asm("{ .reg .u64 t; cvta.to.shared.u64 t, %1; cvt.u32.u64 %0, t; }" : "=r"(a) : "l"(p));
    return a;
}
__device__ __forceinline__ void ldsm4(u32* r, u32 addr) {
    asm volatile("ldmatrix.sync.aligned.m8n8.x4.shared.b16 {%0,%1,%2,%3}, [%4];"
        : "=r"(r[0]), "=r"(r[1]), "=r"(r[2]), "=r"(r[3]) : "r"(addr));
}
__device__ __forceinline__ void stsm4(u32 addr, u32 r0, u32 r1, u32 r2, u32 r3) {
    asm volatile("stmatrix.sync.aligned.m8n8.x4.shared.b16 [%0], {%1,%2,%3,%4};"
        :: "r"(addr), "r"(r0), "r"(r1), "r"(r2), "r"(r3) : "memory");
}
__device__ __forceinline__ void mma16816(float* c, const u32* a, u32 b0, u32 b1) {
    asm volatile("mma.sync.aligned.m16n8k16.row.col.f32.bf16.bf16.f32 "
        "{%0,%1,%2,%3}, {%4,%5,%6,%7}, {%8,%9}, {%0,%1,%2,%3};"
        : "+f"(c[0]), "+f"(c[1]), "+f"(c[2]), "+f"(c[3])
        : "r"(a[0]), "r"(a[1]), "r"(a[2]), "r"(a[3]), "r"(b0), "r"(b1));
}
__device__ __forceinline__ void sts_bf16_at(u32 addr, float v) {
    unsigned short b; asm("cvt.rn.bf16.f32 %0, %1;" : "=h"(b) : "f"(v));
    asm volatile("st.shared.b16 [%0], %1;" :: "r"(addr), "h"(b));
}
__device__ __forceinline__ u32 lds_u32(u32 addr) {
    u32 v; asm volatile("ld.shared.b32 %0, [%1];" : "=r"(v) : "r"(addr));
    return v;
}
__device__ __forceinline__ u32 pack_bf16x2(float hi, float lo) {
    u32 p; asm("cvt.rn.bf16x2.f32 %0, %1, %2;" : "=r"(p) : "f"(hi), "f"(lo));
    return p;
}
// group barrier: 8 warps (256 threads), ids 1/2
#define GBAR(id) asm volatile("bar.sync %0, %1;" :: "r"(id), "r"(256) : "memory")

// softplus(100t)/100; 64-entry midpoint LUT, bank-replicated (conflict-free)
__device__ __forceinline__ float sp_lut(float t, const float* lut_lane) {
    float s = fminf(fabsf(t) * 800.0f, 63.0f);
    int i = (int)s;
    return fmaxf(t, 0.f) + 0.01f * lut_lane[i << 5];
}

// ================= pre-pass: tiled transpose (fp32 -> fp16) =================
__global__ void transpose_planes_kernel(const float* __restrict__ planes) {
    __shared__ float t[36*301];
    const int b = blockIdx.x;            // p*300 + y
    const int p = b / GRID_R;
    const int y = b % GRID_R;
    const int tid = threadIdx.x;
    for (int idx = tid; idx < 36*GRID_R; idx += blockDim.x) {
        int c = idx / GRID_R, x = idx % GRID_R;
        t[c*301 + x] = planes[((size_t)(p*NCOMP + c)*GRID_R + y)*GRID_R + x];
    }
    __syncthreads();
    __half* dst = g_planesT + (size_t)(p*GRID_R + y)*GRID_R*NCOMP;
    for (int idx = tid; idx < GRID_R*36; idx += blockDim.x) {
        int x = idx / 36, c = idx % 36;
        dst[idx] = __float2half(t[c*301 + x]);
    }
}

__global__ void prep_weights_kernel(const float* __restrict__ lines,
                                    const float* __restrict__ w1,
                                    const float* __restrict__ b1,
                                    const float* __restrict__ w2) {
    int idx = blockIdx.x*blockDim.x + threadIdx.x;
    if (idx < 3*GRID_R*NCOMP) {
        int c = idx % NCOMP;
        int t = idx / NCOMP;
        int z = t % GRID_R;
        int p = t / GRID_R;
        g_linesT[idx] = lines[(p*NCOMP + c)*GRID_R + z];
    }
    if (idx < 256*144) {
        int k = idx % 144, n = idx / 144;
        float v = (k < IN_CH) ? w1[n*IN_CH + k] : ((k == IN_CH) ? b1[n] : 0.f);
        unsigned short b; asm("cvt.rn.bf16.f32 %0, %1;" : "=h"(b) : "f"(v));
        g_w1bf[idx] = b;
    }
    if (idx < 128*256) {
        float v = w2[idx];
        unsigned short b; asm("cvt.rn.bf16.f32 %0, %1;" : "=h"(b) : "f"(v));
        g_w2bf[idx] = b;
    }
}

// ================= kernel A: gather + embed -> fragment-packed X =================
__global__ __launch_bounds__(GTHREADS)
void gather_kernel(const float* __restrict__ xyz) {
    extern __shared__ __align__(16) char sg[];
    const u32 sa = smem_u32(sg);

    const int tid  = threadIdx.x;
    const int w    = tid >> 5;
    const int lane = tid & 31;
    const int blk  = blockIdx.x;
    const int base = blk * TILE_M;
    const u32 rb   = sa + (u32)w * (16*304);

    for (int t = 0; t < 16; t++) {
        const int pt = base + w*16 + t;
        const u32 xrow = rb + (u32)t * 304;
        const float x0 = xyz[pt*3 + 0];
        const float x1 = xyz[pt*3 + 1];
        const float x2 = xyz[pt*3 + 2];

        if (lane < 21) {
            float v;
            if (lane < 3) v = (lane == 0) ? x0 : ((lane == 1) ? x1 : x2);
            else {
                int tt = lane - 3;
                int iscos = (tt >= 9);
                int q = iscos ? tt - 9 : tt;
                int dim = q / 3, fr = q % 3;
                float xv = (dim == 0) ? x0 : ((dim == 1) ? x1 : x2);
                float ang = xv * (float)(1 << fr);
                v = iscos ? __cosf(ang) : __sinf(ang);
            }
            sts_bf16_at(xrow + lane*2, v);
        }
        if (lane < 15)
            sts_bf16_at(xrow + (129 + lane)*2, (lane == 0) ? 1.0f : 0.f);

        #pragma unroll
        for (int p = 0; p < 3; p++) {
            float px = (p == 2) ? x1 : x0;
            float py = (p == 0) ? x1 : x2;
            float pz = (p == 0) ? x2 : ((p == 1) ? x1 : x0);
            float fx = (px + 1.f) * 0.5f * (GRID_R - 1);
            float fy = (py + 1.f) * 0.5f * (GRID_R - 1);
            float fz = (pz + 1.f) * 0.5f * (GRID_R - 1);
            int ix = min(max((int)floorf(fx), 0), GRID_R - 2);
            int iy = min(max((int)floorf(fy), 0), GRID_R - 2);
            int iz = min(max((int)floorf(fz), 0), GRID_R - 2);
            float tx = fx - (float)ix, ty = fy - (float)iy, tz = fz - (float)iz;
            const __half* pb = g_planesT + ((size_t)(p*GRID_R + iy)*GRID_R + ix)*NCOMP;
            const float*  lb = g_linesT  + (size_t)(p*GRID_R + iz)*NCOMP;
            float w00 = (1.f - tx) * (1.f - ty);
            float w01 = tx * (1.f - ty);
            float w10 = (1.f - tx) * ty;
            float w11 = tx * ty;
            #pragma unroll
            for (int ci = 0; ci < 2; ci++) {
                int cc = ci*32 + lane;
                if (cc < NCOMP) {
                    float v00 = __half2float(pb[cc]);
                    float v01 = __half2float(pb[NCOMP + cc]);
                    float v10 = __half2float(pb[GRID_R*NCOMP + cc]);
                    float v11 = __half2float(pb[GRID_R*NCOMP + NCOMP + cc]);
                    float pv = v00*w00 + v01*w01 + v10*w10 + v11*w11;
                    float l0 = lb[cc], l1 = lb[NCOMP + cc];
                    float lv = l0 + tz * (l1 - l0);
                    sts_bf16_at(xrow + (21 + p*36 + cc)*2, pv * lv);
                }
            }
        }
    }
    __syncwarp();

    const int g  = lane >> 2;
    const int tg = lane & 3;
    uint4* dst = g_X + ((size_t)(blk*8 + w)*9)*32 + lane;
    #pragma unroll
    for (int ks = 0; ks < 9; ks++) {
        u32 a0 = lds_u32(rb + (u32)g*304     + ks*32 + tg*4);
        u32 a1 = lds_u32(rb + (u32)(g+8)*304 + ks*32 + tg*4);
        u32 a2 = lds_u32(rb + (u32)g*304     + ks*32 + tg*4 + 16);
        u32 a3 = lds_u32(rb + (u32)(g+8)*304 + ks*32 + tg*4 + 16);
        dst[ks*32] = make_uint4(a0, a1, a2, a3);
    }
}

// ================= kernel B: MLP, 2 independent 8-warp groups =================
__global__ __launch_bounds__(MTHREADS, 1)
void mlp_kernel(const float* __restrict__ w2,
                const float* __restrict__ b2,
                float* __restrict__ out)
{
    extern __shared__ __align__(16) char sm[];
    const u32 sa = smem_u32(sm);

    const int tid  = threadIdx.x;
    const int lane = tid & 31;
    const int grp  = tid >> 8;       // 0 / 1
    const int gt   = tid & 255;      // thread-in-group
    const int wg   = gt >> 5;        // warp-in-group 0..7
    const int r1   = wg & 1;         // rows 32*r1 of group's 64
    const int c1   = wg >> 1;        // MMA1 cols 64*c1 of 256
    const int c2   = wg >> 1;        // MMA2 cols 32*c2 of 128
    const int lg   = lane >> 2;
    const int tg   = lane & 3;
    const int barid = 1 + grp;

    const u32 sa_w1 = sa + W1S_OFF;
    const u32 sa_w2 = sa + W2S_OFF;
    const u32 sa_h  = sa + HS_OFF + (u32)grp * HS_GRP;
    float* lutf  = (float*)(sm + LUT_OFF);
    float* w2c   = (float*)(sm + W2C_OFF);
    float* b2s   = (float*)(sm + B2S_OFF);
    float* c128  = (float*)(sm + C128_OFF) + grp*256;             // [4][64]
    float* stage = (float*)(sm + HS_OFF + grp*HS_GRP);            // overlays H

    for (int idx = tid; idx < 4608; idx += MTHREADS) {
        int n = idx / 18, cc = idx % 18;
        *(uint4*)(sm + W1S_OFF + n*304 + cc*16) = ((const uint4*)g_w1bf)[idx];
    }
    for (int idx = tid; idx < 4096; idx += MTHREADS) {
        int n = idx >> 5, cc = idx & 31;
        *(uint4*)(sm + W2S_OFF + n*528 + cc*16) = ((const uint4*)g_w2bf)[idx];
    }
    for (int i = tid; i < 2048; i += MTHREADS) {
        int e = i >> 5;
        lutf[i] = log1pf(expf(-((float)e + 0.5f) * 0.125f));
    }
    if (tid < 256) w2c[tid] = w2[128*SDF_DIM + tid];
    if (tid < 129) b2s[tid] = b2[tid];
    __syncthreads();

    const float* lut_lane = lutf + lane;

    // per-warp constants
    float2 b2v[4];       // MMA2 epilogue bias, cols 32*c2+8*nb+2*tg
    #pragma unroll
    for (int nb = 0; nb < 4; nb++) {
        int C = 32*c2 + 8*nb + 2*tg;
        b2v[nb] = make_float2(b2s[C], b2s[C+1]);
    }
    const float b2_128 = b2s[128];

    const int st_row = ((lane >> 3) & 1)*8 + (lane & 7);
    const int st_col = (lane >> 4)*8;

    for (int u = blockIdx.x*2 + grp; u < N_UNITS; u += gridDim.x*2) {
        const int base = u * 64;

        // ---- MMA1: rows 32*r1..+31 (of 64), cols 64*c1..+63 ----
        float acc[2][8][4];
        #pragma unroll
        for (int mb = 0; mb < 2; mb++)
            #pragma unroll
            for (int nb = 0; nb < 8; nb++)
                #pragma unroll
                for (int k = 0; k < 4; k++) acc[mb][nb][k] = 0.f;

        const uint4* asrc0 = g_X + ((size_t)(u*4 + 2*r1    )*9)*32 + lane;
        const uint4* asrc1 = g_X + ((size_t)(u*4 + 2*r1 + 1)*9)*32 + lane;
        const u32 bn0 = 64*c1 + (lane & 7) + ((lane >> 4) & 1)*8;

        uint4 af0 = asrc0[0];
        uint4 af1 = asrc1[0];
        #pragma unroll
        for (int ks = 0; ks < 9; ks++) {
            uint4 nf0, nf1;
            if (ks < 8) { nf0 = asrc0[(ks+1)*32]; nf1 = asrc1[(ks+1)*32]; }
            const u32 bk = ks*32 + ((lane >> 3) & 1)*16;
            #pragma unroll
            for (int q = 0; q < 4; q++) {
                u32 b[4];
                ldsm4(b, sa_w1 + (bn0 + 16*q)*304 + bk);
                mma16816(acc[0][2*q],   (const u32*)&af0, b[0], b[1]);
                mma16816(acc[1][2*q],   (const u32*)&af1, b[0], b[1]);
                mma16816(acc[0][2*q+1], (const u32*)&af0, b[2], b[3]);
                mma16816(acc[1][2*q+1], (const u32*)&af1, b[2], b[3]);
            }
            af0 = nf0; af1 = nf1;
        }

        // ---- softplus + H store via stmatrix + col128 partials ----
        {
            float s128[2][2] = {{0.f,0.f},{0.f,0.f}};
            #pragma unroll
            for (int mb = 0; mb < 2; mb++) {
                const u32 rowbase = sa_h + (u32)(32*r1 + 16*mb + st_row)*528;
                #pragma unroll
                for (int nbp = 0; nbp < 4; nbp++) {
                    const int nb0 = 2*nbp;
                    float* d0 = acc[mb][nb0];
                    float* d1 = acc[mb][nb0+1];
                    float h00 = sp_lut(d0[0], lut_lane);
                    float h01 = sp_lut(d0[1], lut_lane);
                    float h02 = sp_lut(d0[2], lut_lane);
                    float h03 = sp_lut(d0[3], lut_lane);
                    float h10 = sp_lut(d1[0], lut_lane);
                    float h11 = sp_lut(d1[1], lut_lane);
                    float h12 = sp_lut(d1[2], lut_lane);
                    float h13 = sp_lut(d1[3], lut_lane);
                    const int C0 = 64*c1 + 8*nb0 + 2*tg;
                    float wc00 = w2c[C0],   wc01 = w2c[C0+1];
                    float wc10 = w2c[C0+8], wc11 = w2c[C0+9];
                    s128[mb][0] = fmaf(h00, wc00, fmaf(h01, wc01, s128[mb][0]));
                    s128[mb][1] = fmaf(h02, wc00, fmaf(h03, wc01, s128[mb][1]));
                    s128[mb][0] = fmaf(h10, wc10, fmaf(h11, wc11, s128[mb][0]));
                    s128[mb][1] = fmaf(h12, wc10, fmaf(h13, wc11, s128[mb][1]));
                    u32 p0 = pack_bf16x2(h01, h00);
                    u32 p1 = pack_bf16x2(h03, h02);
                    u32 p2 = pack_bf16x2(h11, h10);
                    u32 p3 = pack_bf16x2(h13, h12);
                    stsm4(rowbase + (u32)(64*c1 + 8*nb0 + st_col)*2, p0, p1, p2, p3);
                }
            }
            #pragma unroll
            for (int mb = 0; mb < 2; mb++)
                #pragma unroll
                for (int hh = 0; hh < 2; hh++) {
                    float v = s128[mb][hh];
                    v += __shfl_xor_sync(0xffffffffu, v, 1);
                    v += __shfl_xor_sync(0xffffffffu, v, 2);
                    s128[mb][hh] = v;
                }
            if (tg == 0) {
                float* dst = c128 + c1*64;
                #pragma unroll
                for (int mb = 0; mb < 2; mb++) {
                    dst[32*r1 + 16*mb + lg]     = s128[mb][0];
                    dst[32*r1 + 16*mb + lg + 8] = s128[mb][1];
                }
            }
        }
        GBAR(barid);   // H + c128 visible within group

        // ---- MMA2: rows 32*r1..+31, cols 32*c2..+31 ----
        float acc2[2][4][4];
        #pragma unroll
        for (int mb = 0; mb < 2; mb++)
            #pragma unroll
            for (int nb = 0; nb < 4; nb++)
                #pragma unroll
                for (int k = 0; k < 4; k++) acc2[mb][nb][k] = 0.f;

        const u32 bn0b = 32*c2 + (lane & 7) + ((lane >> 4) & 1)*8;
        #pragma unroll 4
        for (int ks = 0; ks < 16; ks++) {
            u32 a0[4], a1[4];
            const u32 abase = sa_h + (u32)(32*r1 + (lane & 15))*528 + ks*32 + (lane >> 4)*16;
            ldsm4(a0, abase);
            ldsm4(a1, abase + 16*528);
            const u32 bk = ks*32 + ((lane >> 3) & 1)*16;
            #pragma unroll
            for (int q = 0; q < 2; q++) {
                u32 b[4];
                ldsm4(b, sa_w2 + (bn0b + 16*q)*528 + bk);
                mma16816(acc2[0][2*q],   a0, b[0], b[1]);
                mma16816(acc2[1][2*q],   a1, b[0], b[1]);
                mma16816(acc2[0][2*q+1], a0, b[2], b[3]);
                mma16816(acc2[1][2*q+1], a1, b[2], b[3]);
            }
        }
        GBAR(barid);   // group H reads done; region becomes stage

        // ---- stage + coalesced store ----
        #pragma unroll
        for (int mb = 0; mb < 2; mb++) {
            const int R0 = 32*r1 + 16*mb + lg;
            #pragma unroll
            for (int nb = 0; nb < 4; nb++) {
                const int C = 32*c2 + 8*nb + 2*tg;
                float* d = acc2[mb][nb];
                *(float2*)(stage + R0*130 + C)     = make_float2(d[0] + b2v[nb].x, d[1] + b2v[nb].y);
                *(float2*)(stage + (R0+8)*130 + C) = make_float2(d[2] + b2v[nb].x, d[3] + b2v[nb].y);
            }
        }
        if (gt < 64) {
            float s = b2_128;
            #pragma unroll
            for (int k = 0; k < 4; k++) s += c128[k*64 + gt];
            stage[gt*130 + 128] = s;
        }
        GBAR(barid);
        {
            float* op = out + (size_t)base * OUT_CH;
            for (int i = gt; i < 64*OUT_CH; i += 256) {
                int rr = i / OUT_CH;
                int cc = i - rr*OUT_CH;
                op[i] = stage[rr*130 + cc];
            }
        }
        GBAR(barid);   // stage reads done before next unit's H overwrites
    }
}

// ================= launch =================
extern "C" void kernel_launch(void* const* d_in, const int* in_sizes, int n_in,
                              void* d_out, int out_size) {
    const float* xyz    = (const float*)d_in[0];
    const float* planes = (const float*)d_in[1];
    const float* lines  = (const float*)d_in[2];
    const float* w1     = (const float*)d_in[3];
    const float* b1     = (const float*)d_in[4];
    const float* w2     = (const float*)d_in[5];
    const float* b2     = (const float*)d_in[6];
    float* out = (float*)d_out;

    int sms = 148;
    cudaDeviceGetAttribute(&sms, cudaDevAttrMultiProcessorCount, 0);

    transpose_planes_kernel<<<3*GRID_R, 256>>>(planes);
    prep_weights_kernel<<<(256*144 + 255)/256, 256>>>(lines, w1, b1, w2);
    gather_kernel<<<N_TILES, GTHREADS, 8*16*304>>>(xyz);

    cudaFuncSetAttribute(mlp_kernel, cudaFuncAttributeMaxDynamicSharedMemorySize, SMEM_B);
    mlp_kernel<<<sms, MTHREADS, SMEM_B>>>(w2, b2, out);
}

// round 15
// speedup vs baseline: 1.0529x; 1.0529x over previous
#include <cuda_runtime.h>
#include <cuda_bf16.h>
#include <cuda_fp16.h>
#include <math.h>
#include <cstdint>

#define N_PTS   524288
#define GRID_R  300
#define NCOMP   36
#define SDF_DIM 256
#define IN_CH   129
#define OUT_CH  129
#define TILE_M  128
#define N_TILES (N_PTS / TILE_M)      // 4096
#define N_UNITS (N_PTS / 64)          // 8192 64-row units

#define GTHREADS 256
#define MTHREADS 512                  // 16 warps = 2 groups x 8 warps

// ---- mlp kernel smem map (bytes) ----
#define W1S_OFF  0                    // 256 x 304B = 77824
#define W2S_OFF  77824                // 128 x 528B = 67584
#define HS_OFF   145408               // 2 groups x 64 x 528B = 67584 (stage overlays)
#define HS_GRP   33792                // per-group H bytes
#define LUT_OFF  212992               // 64 entries x 32 banks x 4B = 8192
#define W2C_OFF  221184               // 256 * 4
#define B2S_OFF  222208               // 132 * 4
#define C128_OFF 222736               // 2 grp x 4 x 64 x 4 = 2048
#define SMEM_B   224784

typedef unsigned int u32;

__device__ __half g_planesT[3*GRID_R*GRID_R*NCOMP];        // fp16: 19.4MB, L2-resident
__device__ float  g_linesT [3*GRID_R*NCOMP];
__device__ __align__(16) unsigned short g_w1bf[256*144];   // [n][k], k129=b1, 130..143=0
__device__ __align__(16) unsigned short g_w2bf[128*256];   // [n][k]
__device__ uint4 g_X[N_TILES*8*9*32];                      // A-fragments (16-row strips)

__device__ __forceinline__ u32 smem_u32(const void* p) {
    u32 a; asm("{ .reg .u64 t; cvta.to.shared.u64 t, %1; cvt.u32.u64 %0, t; }" : "=r"(a) : "l"(p));
    return a;
}
__device__ __forceinline__ void ldsm4(u32* r, u32 addr) {
    asm volatile("ldmatrix.sync.aligned.m8n8.x4.shared.b16 {%0,%1,%2,%3}, [%4];"
        : "=r"(r[0]), "=r"(r[1]), "=r"(r[2]), "=r"(r[3]) : "r"(addr));
}
__device__ __forceinline__ void stsm4(u32 addr, u32 r0, u32 r1, u32 r2, u32 r3) {
    asm volatile("stmatrix.sync.aligned.m8n8.x4.shared.b16 [%0], {%1,%2,%3,%4};"
        :: "r"(addr), "r"(r0), "r"(r1), "r"(r2), "r"(r3) : "memory");
}
__device__ __forceinline__ void mma16816(float* c, const u32* a, u32 b0, u32 b1) {
    asm volatile("mma.sync.aligned.m16n8k16.row.col.f32.bf16.bf16.f32 "
        "{%0,%1,%2,%3}, {%4,%5,%6,%7}, {%8,%9}, {%0,%1,%2,%3};"
        : "+f"(c[0]), "+f"(c[1]), "+f"(c[2]), "+f"(c[3])
        : "r"(a[0]), "r"(a[1]), "r"(a[2]), "r"(a[3]), "r"(b0), "r"(b1));
}
__device__ __forceinline__ void sts_bf16_at(u32 addr, float v) {
    unsigned short b; asm("cvt.rn.bf16.f32 %0, %1;" : "=h"(b) : "f"(v));
    asm volatile("st.shared.b16 [%0], %1;" :: "r"(addr), "h"(b));
}
__device__ __forceinline__ u32 lds_u32(u32 addr) {
    u32 v; asm volatile("ld.shared.b32 %0, [%1];" : "=r"(v) : "r"(addr));
    return v;
}
__device__ __forceinline__ u32 pack_bf16x2(float hi, float lo) {
    u32 p; asm("cvt.rn.bf16x2.f32 %0, %1, %2;" : "=r"(p) : "f"(hi), "f"(lo));
    return p;
}
// group barrier: 8 warps (256 threads), ids 1/2
#define GBAR(id) asm volatile("bar.sync %0, %1;" :: "r"(id), "r"(256) : "memory")

// softplus(100t)/100; 64-entry midpoint LUT, bank-replicated (conflict-free)
__device__ __forceinline__ float sp_lut(float t, const float* lut_lane) {
    float s = fminf(fabsf(t) * 800.0f, 63.0f);
    int i = (int)s;
    return fmaxf(t, 0.f) + 0.01f * lut_lane[i << 5];
}

// ================= pre-pass: tiled transpose (fp32 -> fp16) =================
__global__ void transpose_planes_kernel(const float* __restrict__ planes) {
    __shared__ float t[36*301];
    const int b = blockIdx.x;            // p*300 + y
    const int p = b / GRID_R;
    const int y = b % GRID_R;
    const int tid = threadIdx.x;
    for (int idx = tid; idx < 36*GRID_R; idx += blockDim.x) {
        int c = idx / GRID_R, x = idx % GRID_R;
        t[c*301 + x] = planes[((size_t)(p*NCOMP + c)*GRID_R + y)*GRID_R + x];
    }
    __syncthreads();
    __half* dst = g_planesT + (size_t)(p*GRID_R + y)*GRID_R*NCOMP;
    for (int idx = tid; idx < GRID_R*36; idx += blockDim.x) {
        int x = idx / 36, c = idx % 36;
        dst[idx] = __float2half(t[c*301 + x]);
    }
}

__global__ void prep_weights_kernel(const float* __restrict__ lines,
                                    const float* __restrict__ w1,
                                    const float* __restrict__ b1,
                                    const float* __restrict__ w2) {
    int idx = blockIdx.x*blockDim.x + threadIdx.x;
    if (idx < 3*GRID_R*NCOMP) {
        int c = idx % NCOMP;
        int t = idx / NCOMP;
        int z = t % GRID_R;
        int p = t / GRID_R;
        g_linesT[idx] = lines[(p*NCOMP + c)*GRID_R + z];
    }
    if (idx < 256*144) {
        int k = idx % 144, n = idx / 144;
        float v = (k < IN_CH) ? w1[n*IN_CH + k] : ((k == IN_CH) ? b1[n] : 0.f);
        unsigned short b; asm("cvt.rn.bf16.f32 %0, %1;" : "=h"(b) : "f"(v));
        g_w1bf[idx] = b;
    }
    if (idx < 128*256) {
        float v = w2[idx];
        unsigned short b; asm("cvt.rn.bf16.f32 %0, %1;" : "=h"(b) : "f"(v));
        g_w2bf[idx] = b;
    }
}

// ================= kernel A: gather + embed -> fragment-packed X =================
__global__ __launch_bounds__(GTHREADS)
void gather_kernel(const float* __restrict__ xyz) {
    extern __shared__ __align__(16) char sg[];
    const u32 sa = smem_u32(sg);

    const int tid  = threadIdx.x;
    const int w    = tid >> 5;
    const int lane = tid & 31;
    const int blk  = blockIdx.x;
    const int base = blk * TILE_M;
    const u32 rb   = sa + (u32)w * (16*304);

    // ---- preload this warp's 16 points (48 floats) coalesced, broadcast via shfl ----
    float vA, vB = 0.f;
    {
        const float* xb = xyz + (size_t)(base + w*16)*3;
        vA = xb[lane];
        if (lane < 16) vB = xb[32 + lane];
    }

    #pragma unroll 2
    for (int t = 0; t < 16; t++) {
        const u32 xrow = rb + (u32)t * 304;
        const int i0 = 3*t, i1 = 3*t + 1, i2 = 3*t + 2;
        const float x0 = (i0 < 32) ? __shfl_sync(0xffffffffu, vA, i0) : __shfl_sync(0xffffffffu, vB, i0 - 32);
        const float x1 = (i1 < 32) ? __shfl_sync(0xffffffffu, vA, i1) : __shfl_sync(0xffffffffu, vB, i1 - 32);
        const float x2 = (i2 < 32) ? __shfl_sync(0xffffffffu, vA, i2) : __shfl_sync(0xffffffffu, vB, i2 - 32);

        if (lane < 21) {
            float v;
            if (lane < 3) v = (lane == 0) ? x0 : ((lane == 1) ? x1 : x2);
            else {
                int tt = lane - 3;
                int iscos = (tt >= 9);
                int q = iscos ? tt - 9 : tt;
                int dim = q / 3, fr = q % 3;
                float xv = (dim == 0) ? x0 : ((dim == 1) ? x1 : x2);
                float ang = xv * (float)(1 << fr);
                v = iscos ? __cosf(ang) : __sinf(ang);
            }
            sts_bf16_at(xrow + lane*2, v);
        }
        if (lane < 15)
            sts_bf16_at(xrow + (129 + lane)*2, (lane == 0) ? 1.0f : 0.f);

        #pragma unroll
        for (int p = 0; p < 3; p++) {
            float px = (p == 2) ? x1 : x0;
            float py = (p == 0) ? x1 : x2;
            float pz = (p == 0) ? x2 : ((p == 1) ? x1 : x0);
            float fx = (px + 1.f) * 0.5f * (GRID_R - 1);
            float fy = (py + 1.f) * 0.5f * (GRID_R - 1);
            float fz = (pz + 1.f) * 0.5f * (GRID_R - 1);
            int ix = min(max((int)floorf(fx), 0), GRID_R - 2);
            int iy = min(max((int)floorf(fy), 0), GRID_R - 2);
            int iz = min(max((int)floorf(fz), 0), GRID_R - 2);
            float tx = fx - (float)ix, ty = fy - (float)iy, tz = fz - (float)iz;
            const __half2* pb2 = (const __half2*)(g_planesT + ((size_t)(p*GRID_R + iy)*GRID_R + ix)*NCOMP);
            const float*   lb  = g_linesT + (size_t)(p*GRID_R + iz)*NCOMP;
            float w00 = (1.f - tx) * (1.f - ty);
            float w01 = tx * (1.f - ty);
            float w10 = (1.f - tx) * ty;
            float w11 = tx * ty;
            if (lane < 18) {   // 2 channels per lane: cc = 2*lane, 2*lane+1
                float2 a00 = __half22float2(pb2[lane]);
                float2 a01 = __half22float2(pb2[18 + lane]);                      // +NCOMP
                float2 a10 = __half22float2(pb2[(GRID_R*NCOMP)/2 + lane]);        // +row
                float2 a11 = __half22float2(pb2[(GRID_R*NCOMP + NCOMP)/2 + lane]);
                float pvx = a00.x*w00 + a01.x*w01 + a10.x*w10 + a11.x*w11;
                float pvy = a00.y*w00 + a01.y*w01 + a10.y*w10 + a11.y*w11;
                float2 l0 = ((const float2*)lb)[lane];
                float2 l1 = ((const float2*)(lb + NCOMP))[lane];
                float lvx = l0.x + tz * (l1.x - l0.x);
                float lvy = l0.y + tz * (l1.y - l0.y);
                const u32 ad = xrow + (u32)(21 + p*36 + 2*lane)*2;
                sts_bf16_at(ad,     pvx * lvx);
                sts_bf16_at(ad + 2, pvy * lvy);
            }
        }
    }
    __syncwarp();

    const int g  = lane >> 2;
    const int tg = lane & 3;
    uint4* dst = g_X + ((size_t)(blk*8 + w)*9)*32 + lane;
    #pragma unroll
    for (int ks = 0; ks < 9; ks++) {
        u32 a0 = lds_u32(rb + (u32)g*304     + ks*32 + tg*4);
        u32 a1 = lds_u32(rb + (u32)(g+8)*304 + ks*32 + tg*4);
        u32 a2 = lds_u32(rb + (u32)g*304     + ks*32 + tg*4 + 16);
        u32 a3 = lds_u32(rb + (u32)(g+8)*304 + ks*32 + tg*4 + 16);
        dst[ks*32] = make_uint4(a0, a1, a2, a3);
    }
}

// ================= kernel B: MLP, 2 independent 8-warp groups =================
__global__ __launch_bounds__(MTHREADS, 1)
void mlp_kernel(const float* __restrict__ w2,
                const float* __restrict__ b2,
                float* __restrict__ out)
{
    extern __shared__ __align__(16) char sm[];
    const u32 sa = smem_u32(sm);

    const int tid  = threadIdx.x;
    const int lane = tid & 31;
    const int grp  = tid >> 8;       // 0 / 1
    const int gt   = tid & 255;      // thread-in-group
    const int wg   = gt >> 5;        // warp-in-group 0..7
    const int r1   = wg & 1;         // rows 32*r1 of group's 64
    const int c1   = wg >> 1;        // MMA1 cols 64*c1 of 256
    const int c2   = wg >> 1;        // MMA2 cols 32*c2 of 128
    const int lg   = lane >> 2;
    const int tg   = lane & 3;
    const int barid = 1 + grp;

    const u32 sa_w1 = sa + W1S_OFF;
    const u32 sa_w2 = sa + W2S_OFF;
    const u32 sa_h  = sa + HS_OFF + (u32)grp * HS_GRP;
    float* lutf  = (float*)(sm + LUT_OFF);
    float* w2c   = (float*)(sm + W2C_OFF);
    float* b2s   = (float*)(sm + B2S_OFF);
    float* c128  = (float*)(sm + C128_OFF) + grp*256;             // [4][64]
    float* stage = (float*)(sm + HS_OFF + grp*HS_GRP);            // overlays H

    for (int idx = tid; idx < 4608; idx += MTHREADS) {
        int n = idx / 18, cc = idx % 18;
        *(uint4*)(sm + W1S_OFF + n*304 + cc*16) = ((const uint4*)g_w1bf)[idx];
    }
    for (int idx = tid; idx < 4096; idx += MTHREADS) {
        int n = idx >> 5, cc = idx & 31;
        *(uint4*)(sm + W2S_OFF + n*528 + cc*16) = ((const uint4*)g_w2bf)[idx];
    }
    for (int i = tid; i < 2048; i += MTHREADS) {
        int e = i >> 5;
        lutf[i] = log1pf(expf(-((float)e + 0.5f) * 0.125f));
    }
    if (tid < 256) w2c[tid] = w2[128*SDF_DIM + tid];
    if (tid < 129) b2s[tid] = b2[tid];
    __syncthreads();

    const float* lut_lane = lutf + lane;

    // per-warp constants
    float2 b2v[4];       // MMA2 epilogue bias, cols 32*c2+8*nb+2*tg
    #pragma unroll
    for (int nb = 0; nb < 4; nb++) {
        int C = 32*c2 + 8*nb + 2*tg;
        b2v[nb] = make_float2(b2s[C], b2s[C+1]);
    }
    const float b2_128 = b2s[128];

    const int st_row = ((lane >> 3) & 1)*8 + (lane & 7);
    const int st_col = (lane >> 4)*8;

    for (int u = blockIdx.x*2 + grp; u < N_UNITS; u += gridDim.x*2) {
        const int base = u * 64;

        // ---- MMA1: rows 32*r1..+31 (of 64), cols 64*c1..+63 ----
        float acc[2][8][4];
        #pragma unroll
        for (int mb = 0; mb < 2; mb++)
            #pragma unroll
            for (int nb = 0; nb < 8; nb++)
                #pragma unroll
                for (int k = 0; k < 4; k++) acc[mb][nb][k] = 0.f;

        const uint4* asrc0 = g_X + ((size_t)(u*4 + 2*r1    )*9)*32 + lane;
        const uint4* asrc1 = g_X + ((size_t)(u*4 + 2*r1 + 1)*9)*32 + lane;
        const u32 bn0 = 64*c1 + (lane & 7) + ((lane >> 4) & 1)*8;

        uint4 af0 = asrc0[0];
        uint4 af1 = asrc1[0];
        #pragma unroll
        for (int ks = 0; ks < 9; ks++) {
            uint4 nf0, nf1;
            if (ks < 8) { nf0 = asrc0[(ks+1)*32]; nf1 = asrc1[(ks+1)*32]; }
            const u32 bk = ks*32 + ((lane >> 3) & 1)*16;
            #pragma unroll
            for (int q = 0; q < 4; q++) {
                u32 b[4];
                ldsm4(b, sa_w1 + (bn0 + 16*q)*304 + bk);
                mma16816(acc[0][2*q],   (const u32*)&af0, b[0], b[1]);
                mma16816(acc[1][2*q],   (const u32*)&af1, b[0], b[1]);
                mma16816(acc[0][2*q+1], (const u32*)&af0, b[2], b[3]);
                mma16816(acc[1][2*q+1], (const u32*)&af1, b[2], b[3]);
            }
            af0 = nf0; af1 = nf1;
        }

        // ---- softplus + H store via stmatrix + col128 partials ----
        {
            float s128[2][2] = {{0.f,0.f},{0.f,0.f}};
            #pragma unroll
            for (int mb = 0; mb < 2; mb++) {
                const u32 rowbase = sa_h + (u32)(32*r1 + 16*mb + st_row)*528;
                #pragma unroll
                for (int nbp = 0; nbp < 4; nbp++) {
                    const int nb0 = 2*nbp;
                    float* d0 = acc[mb][nb0];
                    float* d1 = acc[mb][nb0+1];
                    float h00 = sp_lut(d0[0], lut_lane);
                    float h01 = sp_lut(d0[1], lut_lane);
                    float h02 = sp_lut(d0[2], lut_lane);
                    float h03 = sp_lut(d0[3], lut_lane);
                    float h10 = sp_lut(d1[0], lut_lane);
                    float h11 = sp_lut(d1[1], lut_lane);
                    float h12 = sp_lut(d1[2], lut_lane);
                    float h13 = sp_lut(d1[3], lut_lane);
                    const int C0 = 64*c1 + 8*nb0 + 2*tg;
                    float wc00 = w2c[C0],   wc01 = w2c[C0+1];
                    float wc10 = w2c[C0+8], wc11 = w2c[C0+9];
                    s128[mb][0] = fmaf(h00, wc00, fmaf(h01, wc01, s128[mb][0]));
                    s128[mb][1] = fmaf(h02, wc00, fmaf(h03, wc01, s128[mb][1]));
                    s128[mb][0] = fmaf(h10, wc10, fmaf(h11, wc11, s128[mb][0]));
                    s128[mb][1] = fmaf(h12, wc10, fmaf(h13, wc11, s128[mb][1]));
                    u32 p0 = pack_bf16x2(h01, h00);
                    u32 p1 = pack_bf16x2(h03, h02);
                    u32 p2 = pack_bf16x2(h11, h10);
                    u32 p3 = pack_bf16x2(h13, h12);
                    stsm4(rowbase + (u32)(64*c1 + 8*nb0 + st_col)*2, p0, p1, p2, p3);
                }
            }
            #pragma unroll
            for (int mb = 0; mb < 2; mb++)
                #pragma unroll
                for (int hh = 0; hh < 2; hh++) {
                    float v = s128[mb][hh];
                    v += __shfl_xor_sync(0xffffffffu, v, 1);
                    v += __shfl_xor_sync(0xffffffffu, v, 2);
                    s128[mb][hh] = v;
                }
            if (tg == 0) {
                float* dst = c128 + c1*64;
                #pragma unroll
                for (int mb = 0; mb < 2; mb++) {
                    dst[32*r1 + 16*mb + lg]     = s128[mb][0];
                    dst[32*r1 + 16*mb + lg + 8] = s128[mb][1];
                }
            }
        }
        GBAR(barid);   // H + c128 visible within group

        // ---- MMA2: rows 32*r1..+31, cols 32*c2..+31 ----
        float acc2[2][4][4];
        #pragma unroll
        for (int mb = 0; mb < 2; mb++)
            #pragma unroll
            for (int nb = 0; nb < 4; nb++)
                #pragma unroll
                for (int k = 0; k < 4; k++) acc2[mb][nb][k] = 0.f;

        const u32 bn0b = 32*c2 + (lane & 7) + ((lane >> 4) & 1)*8;
        #pragma unroll 4
        for (int ks = 0; ks < 16; ks++) {
            u32 a0[4], a1[4];
            const u32 abase = sa_h + (u32)(32*r1 + (lane & 15))*528 + ks*32 + (lane >> 4)*16;
            ldsm4(a0, abase);
            ldsm4(a1, abase + 16*528);
            const u32 bk = ks*32 + ((lane >> 3) & 1)*16;
            #pragma unroll
            for (int q = 0; q < 2; q++) {
                u32 b[4];
                ldsm4(b, sa_w2 + (bn0b + 16*q)*528 + bk);
                mma16816(acc2[0][2*q],   a0, b[0], b[1]);
                mma16816(acc2[1][2*q],   a1, b[0], b[1]);
                mma16816(acc2[0][2*q+1], a0, b[2], b[3]);
                mma16816(acc2[1][2*q+1], a1, b[2], b[3]);
            }
        }
        GBAR(barid);   // group H reads done; region becomes stage

        // ---- stage + coalesced store ----
        #pragma unroll
        for (int mb = 0; mb < 2; mb++) {
            const int R0 = 32*r1 + 16*mb + lg;
            #pragma unroll
            for (int nb = 0; nb < 4; nb++) {
                const int C = 32*c2 + 8*nb + 2*tg;
                float* d = acc2[mb][nb];
                *(float2*)(stage + R0*130 + C)     = make_float2(d[0] + b2v[nb].x, d[1] + b2v[nb].y);
                *(float2*)(stage + (R0+8)*130 + C) = make_float2(d[2] + b2v[nb].x, d[3] + b2v[nb].y);
            }
        }
        if (gt < 64) {
            float s = b2_128;
            #pragma unroll
            for (int k = 0; k < 4; k++) s += c128[k*64 + gt];
            stage[gt*130 + 128] = s;
        }
        GBAR(barid);
        {
            float* op = out + (size_t)base * OUT_CH;
            for (int i = gt; i < 64*OUT_CH; i += 256) {
                int rr = i / OUT_CH;
                int cc = i - rr*OUT_CH;
                op[i] = stage[rr*130 + cc];
            }
        }
        GBAR(barid);   // stage reads done before next unit's H overwrites
    }
}

// ================= launch =================
extern "C" void kernel_launch(void* const* d_in, const int* in_sizes, int n_in,
                              void* d_out, int out_size) {
    const float* xyz    = (const float*)d_in[0];
    const float* planes = (const float*)d_in[1];
    const float* lines  = (const float*)d_in[2];
    const float* w1     = (const float*)d_in[3];
    const float* b1     = (const float*)d_in[4];
    const float* w2     = (const float*)d_in[5];
    const float* b2     = (const float*)d_in[6];
    float* out = (float*)d_out;

    int sms = 148;
    cudaDeviceGetAttribute(&sms, cudaDevAttrMultiProcessorCount, 0);

    transpose_planes_kernel<<<3*GRID_R, 256>>>(planes);
    prep_weights_kernel<<<(256*144 + 255)/256, 256>>>(lines, w1, b1, w2);
    gather_kernel<<<N_TILES, GTHREADS, 8*16*304>>>(xyz);

    cudaFuncSetAttribute(mlp_kernel, cudaFuncAttributeMaxDynamicSharedMemorySize, SMEM_B);
    mlp_kernel<<<sms, MTHREADS, SMEM_B>>>(w2, b2, out);
}

// round 16
// speedup vs baseline: 1.0955x; 1.0404x over previous
#include <cuda_runtime.h>
#include <cuda_bf16.h>
#include <cuda_fp16.h>
#include <math.h>
#include <cstdint>

#define N_PTS   524288
#define GRID_R  300
#define NCOMP   36
#define SDF_DIM 256
#define IN_CH   129
#define OUT_CH  129
#define TILE_M  128
#define N_TILES (N_PTS / TILE_M)      // 4096
#define N_U32   (N_PTS / 32)          // 16384 32-row units

#define GTHREADS 256
#define MTHREADS 512                  // 16 warps = 4 groups x 4 warps

// ---- mlp kernel smem map (bytes) ----
#define W1S_OFF  0                    // 256 x 304B = 77824
#define W2S_OFF  77824                // 128 x 528B = 67584
#define HS_OFF   145408               // 4 groups x 32 x 528B = 67584 (stage overlays)
#define HS_GRP   16896                // per-group H bytes (32 x 528)
#define LUT_OFF  212992               // 64 entries x 32 banks x 4B = 8192
#define W2C_OFF  221184               // 256 * 4
#define B2S_OFF  222208               // 132 * 4
#define C128_OFF 222736               // 4 grp x 4 x 32 x 4 = 2048
#define SMEM_B   224784

typedef unsigned int u32;

__device__ __half g_planesT[3*GRID_R*GRID_R*NCOMP];        // fp16: 19.4MB, L2-resident
__device__ float  g_linesT [3*GRID_R*NCOMP];
__device__ __align__(16) unsigned short g_w1bf[256*144];   // [n][k], k129=b1, 130..143=0
__device__ __align__(16) unsigned short g_w2bf[128*256];   // [n][k]
__device__ uint4 g_X[N_TILES*8*9*32];                      // A-fragments (16-row strips)

__device__ __forceinline__ u32 smem_u32(const void* p) {
    u32 a; asm("{ .reg .u64 t; cvta.to.shared.u64 t, %1; cvt.u32.u64 %0, t; }" : "=r"(a) : "l"(p));
    return a;
}
__device__ __forceinline__ void ldsm4(u32* r, u32 addr) {
    asm volatile("ldmatrix.sync.aligned.m8n8.x4.shared.b16 {%0,%1,%2,%3}, [%4];"
        : "=r"(r[0]), "=r"(r[1]), "=r"(r[2]), "=r"(r[3]) : "r"(addr));
}
__device__ __forceinline__ void stsm4(u32 addr, u32 r0, u32 r1, u32 r2, u32 r3) {
    asm volatile("stmatrix.sync.aligned.m8n8.x4.shared.b16 [%0], {%1,%2,%3,%4};"
        :: "r"(addr), "r"(r0), "r"(r1), "r"(r2), "r"(r3) : "memory");
}
__device__ __forceinline__ void mma16816(float* c, const u32* a, u32 b0, u32 b1) {
    asm volatile("mma.sync.aligned.m16n8k16.row.col.f32.bf16.bf16.f32 "
        "{%0,%1,%2,%3}, {%4,%5,%6,%7}, {%8,%9}, {%0,%1,%2,%3};"
        : "+f"(c[0]), "+f"(c[1]), "+f"(c[2]), "+f"(c[3])
        : "r"(a[0]), "r"(a[1]), "r"(a[2]), "r"(a[3]), "r"(b0), "r"(b1));
}
__device__ __forceinline__ void sts_bf16_at(u32 addr, float v) {
    unsigned short b; asm("cvt.rn.bf16.f32 %0, %1;" : "=h"(b) : "f"(v));
    asm volatile("st.shared.b16 [%0], %1;" :: "r"(addr), "h"(b));
}
__device__ __forceinline__ u32 lds_u32(u32 addr) {
    u32 v; asm volatile("ld.shared.b32 %0, [%1];" : "=r"(v) : "r"(addr));
    return v;
}
__device__ __forceinline__ u32 pack_bf16x2(float hi, float lo) {
    u32 p; asm("cvt.rn.bf16x2.f32 %0, %1, %2;" : "=r"(p) : "f"(hi), "f"(lo));
    return p;
}
// group barrier: 4 warps (128 threads), ids 1..4
#define GBAR(id) asm volatile("bar.sync %0, %1;" :: "r"(id), "r"(128) : "memory")

// softplus(100t)/100; 64-entry midpoint LUT, bank-replicated (conflict-free)
__device__ __forceinline__ float sp_lut(float t, const float* lut_lane) {
    float s = fminf(fabsf(t) * 800.0f, 63.0f);
    int i = (int)s;
    return fmaxf(t, 0.f) + 0.01f * lut_lane[i << 5];
}

// ================= pre-pass: tiled transpose (fp32 -> fp16) =================
__global__ void transpose_planes_kernel(const float* __restrict__ planes) {
    __shared__ float t[36*301];
    const int b = blockIdx.x;            // p*300 + y
    const int p = b / GRID_R;
    const int y = b % GRID_R;
    const int tid = threadIdx.x;
    for (int idx = tid; idx < 36*GRID_R; idx += blockDim.x) {
        int c = idx / GRID_R, x = idx % GRID_R;
        t[c*301 + x] = planes[((size_t)(p*NCOMP + c)*GRID_R + y)*GRID_R + x];
    }
    __syncthreads();
    __half* dst = g_planesT + (size_t)(p*GRID_R + y)*GRID_R*NCOMP;
    for (int idx = tid; idx < GRID_R*36; idx += blockDim.x) {
        int x = idx / 36, c = idx % 36;
        dst[idx] = __float2half(t[c*301 + x]);
    }
}

__global__ void prep_weights_kernel(const float* __restrict__ lines,
                                    const float* __restrict__ w1,
                                    const float* __restrict__ b1,
                                    const float* __restrict__ w2) {
    int idx = blockIdx.x*blockDim.x + threadIdx.x;
    if (idx < 3*GRID_R*NCOMP) {
        int c = idx % NCOMP;
        int t = idx / NCOMP;
        int z = t % GRID_R;
        int p = t / GRID_R;
        g_linesT[idx] = lines[(p*NCOMP + c)*GRID_R + z];
    }
    if (idx < 256*144) {
        int k = idx % 144, n = idx / 144;
        float v = (k < IN_CH) ? w1[n*IN_CH + k] : ((k == IN_CH) ? b1[n] : 0.f);
        unsigned short b; asm("cvt.rn.bf16.f32 %0, %1;" : "=h"(b) : "f"(v));
        g_w1bf[idx] = b;
    }
    if (idx < 128*256) {
        float v = w2[idx];
        unsigned short b; asm("cvt.rn.bf16.f32 %0, %1;" : "=h"(b) : "f"(v));
        g_w2bf[idx] = b;
    }
}

// ================= kernel A: gather + embed -> fragment-packed X =================
__global__ __launch_bounds__(GTHREADS)
void gather_kernel(const float* __restrict__ xyz) {
    extern __shared__ __align__(16) char sg[];
    const u32 sa = smem_u32(sg);

    const int tid  = threadIdx.x;
    const int w    = tid >> 5;
    const int lane = tid & 31;
    const int blk  = blockIdx.x;
    const int base = blk * TILE_M;
    const u32 rb   = sa + (u32)w * (16*304);

    // ---- preload this warp's 16 points (48 floats) coalesced, broadcast via shfl ----
    float vA, vB = 0.f;
    {
        const float* xb = xyz + (size_t)(base + w*16)*3;
        vA = xb[lane];
        if (lane < 16) vB = xb[32 + lane];
    }

    #pragma unroll 2
    for (int t = 0; t < 16; t++) {
        const u32 xrow = rb + (u32)t * 304;
        const int i0 = 3*t, i1 = 3*t + 1, i2 = 3*t + 2;
        const float x0 = (i0 < 32) ? __shfl_sync(0xffffffffu, vA, i0) : __shfl_sync(0xffffffffu, vB, i0 - 32);
        const float x1 = (i1 < 32) ? __shfl_sync(0xffffffffu, vA, i1) : __shfl_sync(0xffffffffu, vB, i1 - 32);
        const float x2 = (i2 < 32) ? __shfl_sync(0xffffffffu, vA, i2) : __shfl_sync(0xffffffffu, vB, i2 - 32);

        if (lane < 21) {
            float v;
            if (lane < 3) v = (lane == 0) ? x0 : ((lane == 1) ? x1 : x2);
            else {
                int tt = lane - 3;
                int iscos = (tt >= 9);
                int q = iscos ? tt - 9 : tt;
                int dim = q / 3, fr = q % 3;
                float xv = (dim == 0) ? x0 : ((dim == 1) ? x1 : x2);
                float ang = xv * (float)(1 << fr);
                v = iscos ? __cosf(ang) : __sinf(ang);
            }
            sts_bf16_at(xrow + lane*2, v);
        }
        if (lane < 15)
            sts_bf16_at(xrow + (129 + lane)*2, (lane == 0) ? 1.0f : 0.f);

        #pragma unroll
        for (int p = 0; p < 3; p++) {
            float px = (p == 2) ? x1 : x0;
            float py = (p == 0) ? x1 : x2;
            float pz = (p == 0) ? x2 : ((p == 1) ? x1 : x0);
            float fx = (px + 1.f) * 0.5f * (GRID_R - 1);
            float fy = (py + 1.f) * 0.5f * (GRID_R - 1);
            float fz = (pz + 1.f) * 0.5f * (GRID_R - 1);
            int ix = min(max((int)floorf(fx), 0), GRID_R - 2);
            int iy = min(max((int)floorf(fy), 0), GRID_R - 2);
            int iz = min(max((int)floorf(fz), 0), GRID_R - 2);
            float tx = fx - (float)ix, ty = fy - (float)iy, tz = fz - (float)iz;
            const __half2* pb2 = (const __half2*)(g_planesT + ((size_t)(p*GRID_R + iy)*GRID_R + ix)*NCOMP);
            const float*   lb  = g_linesT + (size_t)(p*GRID_R + iz)*NCOMP;
            float w00 = (1.f - tx) * (1.f - ty);
            float w01 = tx * (1.f - ty);
            float w10 = (1.f - tx) * ty;
            float w11 = tx * ty;
            if (lane < 18) {   // 2 channels per lane
                float2 a00 = __half22float2(pb2[lane]);
                float2 a01 = __half22float2(pb2[18 + lane]);
                float2 a10 = __half22float2(pb2[(GRID_R*NCOMP)/2 + lane]);
                float2 a11 = __half22float2(pb2[(GRID_R*NCOMP + NCOMP)/2 + lane]);
                float pvx = a00.x*w00 + a01.x*w01 + a10.x*w10 + a11.x*w11;
                float pvy = a00.y*w00 + a01.y*w01 + a10.y*w10 + a11.y*w11;
                float2 l0 = ((const float2*)lb)[lane];
                float2 l1 = ((const float2*)(lb + NCOMP))[lane];
                float lvx = l0.x + tz * (l1.x - l0.x);
                float lvy = l0.y + tz * (l1.y - l0.y);
                const u32 ad = xrow + (u32)(21 + p*36 + 2*lane)*2;
                sts_bf16_at(ad,     pvx * lvx);
                sts_bf16_at(ad + 2, pvy * lvy);
            }
        }
    }
    __syncwarp();

    const int g  = lane >> 2;
    const int tg = lane & 3;
    uint4* dst = g_X + ((size_t)(blk*8 + w)*9)*32 + lane;
    #pragma unroll
    for (int ks = 0; ks < 9; ks++) {
        u32 a0 = lds_u32(rb + (u32)g*304     + ks*32 + tg*4);
        u32 a1 = lds_u32(rb + (u32)(g+8)*304 + ks*32 + tg*4);
        u32 a2 = lds_u32(rb + (u32)g*304     + ks*32 + tg*4 + 16);
        u32 a3 = lds_u32(rb + (u32)(g+8)*304 + ks*32 + tg*4 + 16);
        dst[ks*32] = make_uint4(a0, a1, a2, a3);
    }
}

// ================= kernel B: MLP, 4 independent 4-warp groups =================
__global__ __launch_bounds__(MTHREADS, 1)
void mlp_kernel(const float* __restrict__ w2,
                const float* __restrict__ b2,
                float* __restrict__ out)
{
    extern __shared__ __align__(16) char sm[];
    const u32 sa = smem_u32(sm);

    const int tid  = threadIdx.x;
    const int lane = tid & 31;
    const int grp  = tid >> 7;       // 0..3
    const int gt   = tid & 127;      // thread-in-group
    const int wg   = gt >> 5;        // warp-in-group 0..3
    const int c1   = wg;             // MMA1 cols 64*c1 of 256
    const int c2   = wg;             // MMA2 cols 32*c2 of 128
    const int lg   = lane >> 2;
    const int tg   = lane & 3;
    const int barid = 1 + grp;

    const u32 sa_w1 = sa + W1S_OFF;
    const u32 sa_w2 = sa + W2S_OFF;
    const u32 sa_h  = sa + HS_OFF + (u32)grp * HS_GRP;
    float* lutf  = (float*)(sm + LUT_OFF);
    float* w2c   = (float*)(sm + W2C_OFF);
    float* b2s   = (float*)(sm + B2S_OFF);
    float* c128g = (float*)(sm + C128_OFF) + grp*128;             // [4][32]
    float* stage = (float*)(sm + HS_OFF + grp*HS_GRP);            // overlays H

    for (int idx = tid; idx < 4608; idx += MTHREADS) {
        int n = idx / 18, cc = idx % 18;
        *(uint4*)(sm + W1S_OFF + n*304 + cc*16) = ((const uint4*)g_w1bf)[idx];
    }
    for (int idx = tid; idx < 4096; idx += MTHREADS) {
        int n = idx >> 5, cc = idx & 31;
        *(uint4*)(sm + W2S_OFF + n*528 + cc*16) = ((const uint4*)g_w2bf)[idx];
    }
    for (int i = tid; i < 2048; i += MTHREADS) {
        int e = i >> 5;
        lutf[i] = log1pf(expf(-((float)e + 0.5f) * 0.125f));
    }
    if (tid < 256) w2c[tid] = w2[128*SDF_DIM + tid];
    if (tid < 129) b2s[tid] = b2[tid];
    __syncthreads();

    const float* lut_lane = lutf + lane;

    // per-warp constants (MMA2 epilogue)
    float2 b2v[4];
    #pragma unroll
    for (int nb = 0; nb < 4; nb++) {
        int C = 32*c2 + 8*nb + 2*tg;
        b2v[nb] = make_float2(b2s[C], b2s[C+1]);
    }
    const float b2_128 = b2s[128];

    const int st_row = ((lane >> 3) & 1)*8 + (lane & 7);
    const int st_col = (lane >> 4)*8;

    for (int u = blockIdx.x*4 + grp; u < N_U32; u += gridDim.x*4) {
        const int base = u * 32;

        // ---- MMA1: rows 0..31 of unit, cols 64*c1..+63 ----
        float acc[2][8][4];
        #pragma unroll
        for (int mb = 0; mb < 2; mb++)
            #pragma unroll
            for (int nb = 0; nb < 8; nb++)
                #pragma unroll
                for (int k = 0; k < 4; k++) acc[mb][nb][k] = 0.f;

        const uint4* asrc0 = g_X + ((size_t)(u*2    )*9)*32 + lane;
        const uint4* asrc1 = g_X + ((size_t)(u*2 + 1)*9)*32 + lane;
        const u32 bn0 = 64*c1 + (lane & 7) + ((lane >> 4) & 1)*8;

        uint4 af0 = asrc0[0];
        uint4 af1 = asrc1[0];
        #pragma unroll
        for (int ks = 0; ks < 9; ks++) {
            uint4 nf0, nf1;
            if (ks < 8) { nf0 = asrc0[(ks+1)*32]; nf1 = asrc1[(ks+1)*32]; }
            const u32 bk = ks*32 + ((lane >> 3) & 1)*16;
            #pragma unroll
            for (int q = 0; q < 4; q++) {
                u32 b[4];
                ldsm4(b, sa_w1 + (bn0 + 16*q)*304 + bk);
                mma16816(acc[0][2*q],   (const u32*)&af0, b[0], b[1]);
                mma16816(acc[1][2*q],   (const u32*)&af1, b[0], b[1]);
                mma16816(acc[0][2*q+1], (const u32*)&af0, b[2], b[3]);
                mma16816(acc[1][2*q+1], (const u32*)&af1, b[2], b[3]);
            }
            af0 = nf0; af1 = nf1;
        }

        // ---- softplus + H store via stmatrix + col128 partials ----
        {
            float s128[2][2] = {{0.f,0.f},{0.f,0.f}};
            #pragma unroll
            for (int mb = 0; mb < 2; mb++) {
                const u32 rowbase = sa_h + (u32)(16*mb + st_row)*528;
                #pragma unroll
                for (int nbp = 0; nbp < 4; nbp++) {
                    const int nb0 = 2*nbp;
                    float* d0 = acc[mb][nb0];
                    float* d1 = acc[mb][nb0+1];
                    float h00 = sp_lut(d0[0], lut_lane);
                    float h01 = sp_lut(d0[1], lut_lane);
                    float h02 = sp_lut(d0[2], lut_lane);
                    float h03 = sp_lut(d0[3], lut_lane);
                    float h10 = sp_lut(d1[0], lut_lane);
                    float h11 = sp_lut(d1[1], lut_lane);
                    float h12 = sp_lut(d1[2], lut_lane);
                    float h13 = sp_lut(d1[3], lut_lane);
                    const int C0 = 64*c1 + 8*nb0 + 2*tg;
                    float wc00 = w2c[C0],   wc01 = w2c[C0+1];
                    float wc10 = w2c[C0+8], wc11 = w2c[C0+9];
                    s128[mb][0] = fmaf(h00, wc00, fmaf(h01, wc01, s128[mb][0]));
                    s128[mb][1] = fmaf(h02, wc00, fmaf(h03, wc01, s128[mb][1]));
                    s128[mb][0] = fmaf(h10, wc10, fmaf(h11, wc11, s128[mb][0]));
                    s128[mb][1] = fmaf(h12, wc10, fmaf(h13, wc11, s128[mb][1]));
                    u32 p0 = pack_bf16x2(h01, h00);
                    u32 p1 = pack_bf16x2(h03, h02);
                    u32 p2 = pack_bf16x2(h11, h10);
                    u32 p3 = pack_bf16x2(h13, h12);
                    stsm4(rowbase + (u32)(64*c1 + 8*nb0 + st_col)*2, p0, p1, p2, p3);
                }
            }
            #pragma unroll
            for (int mb = 0; mb < 2; mb++)
                #pragma unroll
                for (int hh = 0; hh < 2; hh++) {
                    float v = s128[mb][hh];
                    v += __shfl_xor_sync(0xffffffffu, v, 1);
                    v += __shfl_xor_sync(0xffffffffu, v, 2);
                    s128[mb][hh] = v;
                }
            if (tg == 0) {
                float* dst = c128g + c1*32;
                #pragma unroll
                for (int mb = 0; mb < 2; mb++) {
                    dst[16*mb + lg]     = s128[mb][0];
                    dst[16*mb + lg + 8] = s128[mb][1];
                }
            }
        }
        GBAR(barid);   // H + c128 visible within group

        // ---- MMA2: rows 0..31, cols 32*c2..+31 ----
        float acc2[2][4][4];
        #pragma unroll
        for (int mb = 0; mb < 2; mb++)
            #pragma unroll
            for (int nb = 0; nb < 4; nb++)
                #pragma unroll
                for (int k = 0; k < 4; k++) acc2[mb][nb][k] = 0.f;

        const u32 bn0b = 32*c2 + (lane & 7) + ((lane >> 4) & 1)*8;
        #pragma unroll 4
        for (int ks = 0; ks < 16; ks++) {
            u32 a0[4], a1[4];
            const u32 abase = sa_h + (u32)(lane & 15)*528 + ks*32 + (lane >> 4)*16;
            ldsm4(a0, abase);
            ldsm4(a1, abase + 16*528);
            const u32 bk = ks*32 + ((lane >> 3) & 1)*16;
            #pragma unroll
            for (int q = 0; q < 2; q++) {
                u32 b[4];
                ldsm4(b, sa_w2 + (bn0b + 16*q)*528 + bk);
                mma16816(acc2[0][2*q],   a0, b[0], b[1]);
                mma16816(acc2[1][2*q],   a1, b[0], b[1]);
                mma16816(acc2[0][2*q+1], a0, b[2], b[3]);
                mma16816(acc2[1][2*q+1], a1, b[2], b[3]);
            }
        }
        GBAR(barid);   // group H reads done; region becomes stage

        // ---- stage + coalesced store ----
        #pragma unroll
        for (int mb = 0; mb < 2; mb++) {
            const int R0 = 16*mb + lg;
            #pragma unroll
            for (int nb = 0; nb < 4; nb++) {
                const int C = 32*c2 + 8*nb + 2*tg;
                float* d = acc2[mb][nb];
                *(float2*)(stage + R0*130 + C)     = make_float2(d[0] + b2v[nb].x, d[1] + b2v[nb].y);
                *(float2*)(stage + (R0+8)*130 + C) = make_float2(d[2] + b2v[nb].x, d[3] + b2v[nb].y);
            }
        }
        if (gt < 32) {
            float s = b2_128;
            #pragma unroll
            for (int k = 0; k < 4; k++) s += c128g[k*32 + gt];
            stage[gt*130 + 128] = s;
        }
        GBAR(barid);
        {
            float* op = out + (size_t)base * OUT_CH;
            for (int i = gt; i < 32*OUT_CH; i += 128) {
                int rr = i / OUT_CH;
                int cc = i - rr*OUT_CH;
                op[i] = stage[rr*130 + cc];
            }
        }
        GBAR(barid);   // stage reads done before next unit's H overwrites
    }
}

// ================= launch =================
extern "C" void kernel_launch(void* const* d_in, const int* in_sizes, int n_in,
                              void* d_out, int out_size) {
    const float* xyz    = (const float*)d_in[0];
    const float* planes = (const float*)d_in[1];
    const float* lines  = (const float*)d_in[2];
    const float* w1     = (const float*)d_in[3];
    const float* b1     = (const float*)d_in[4];
    const float* w2     = (const float*)d_in[5];
    const float* b2     = (const float*)d_in[6];
    float* out = (float*)d_out;

    int sms = 148;
    cudaDeviceGetAttribute(&sms, cudaDevAttrMultiProcessorCount, 0);

    transpose_planes_kernel<<<3*GRID_R, 256>>>(planes);
    prep_weights_kernel<<<(256*144 + 255)/256, 256>>>(lines, w1, b1, w2);
    gather_kernel<<<N_TILES, GTHREADS, 8*16*304>>>(xyz);

    cudaFuncSetAttribute(mlp_kernel, cudaFuncAttributeMaxDynamicSharedMemorySize, SMEM_B);
    mlp_kernel<<<sms, MTHREADS, SMEM_B>>>(w2, b2, out);
}

// round 17
// speedup vs baseline: 1.1004x; 1.0045x over previous
#include <cuda_runtime.h>
#include <cuda_bf16.h>
#include <cuda_fp16.h>
#include <math.h>
#include <cstdint>

#define N_PTS   524288
#define GRID_R  300
#define NCOMP   36
#define SDF_DIM 256
#define IN_CH   129
#define OUT_CH  129
#define TILE_M  128
#define N_TILES (N_PTS / TILE_M)      // 4096
#define N_U32   (N_PTS / 32)          // 16384 32-row units

#define GTHREADS 256
#define MTHREADS 512                  // 16 warps = 4 groups x 4 warps

// ---- mlp kernel smem map (bytes) ----
#define W1S_OFF  0                    // 256 x 304B = 77824
#define W2S_OFF  77824                // 128 x 528B = 67584
#define HS_OFF   145408               // 4 groups x 32 x 528B = 67584 (stage overlays)
#define HS_GRP   16896                // per-group H bytes (32 x 528)
#define LUT_OFF  212992               // 64 entries x 32 banks x 4B = 8192
#define W2C_OFF  221184               // 256 * 4
#define B2S_OFF  222208               // 132 * 4
#define C128_OFF 222736               // 4 grp x 4 x 32 x 4 = 2048
#define SMEM_B   224784

typedef unsigned int u32;

__device__ __half g_planesT[3*GRID_R*GRID_R*NCOMP];        // fp16: 19.4MB, L2-resident
__device__ float  g_linesT [3*GRID_R*NCOMP];
__device__ __align__(16) unsigned short g_w1bf[256*144];   // [n][k], k129=b1, 130..143=0
__device__ __align__(16) unsigned short g_w2bf[128*256];   // [n][k]
__device__ uint4 g_X[N_TILES*8*9*32];                      // A-fragments (16-row strips)

__device__ __forceinline__ u32 smem_u32(const void* p) {
    u32 a; asm("{ .reg .u64 t; cvta.to.shared.u64 t, %1; cvt.u32.u64 %0, t; }" : "=r"(a) : "l"(p));
    return a;
}
__device__ __forceinline__ void ldsm4(u32* r, u32 addr) {
    asm volatile("ldmatrix.sync.aligned.m8n8.x4.shared.b16 {%0,%1,%2,%3}, [%4];"
        : "=r"(r[0]), "=r"(r[1]), "=r"(r[2]), "=r"(r[3]) : "r"(addr));
}
__device__ __forceinline__ void stsm4(u32 addr, u32 r0, u32 r1, u32 r2, u32 r3) {
    asm volatile("stmatrix.sync.aligned.m8n8.x4.shared.b16 [%0], {%1,%2,%3,%4};"
        :: "r"(addr), "r"(r0), "r"(r1), "r"(r2), "r"(r3) : "memory");
}
__device__ __forceinline__ void mma16816(float* c, const u32* a, u32 b0, u32 b1) {
    asm volatile("mma.sync.aligned.m16n8k16.row.col.f32.bf16.bf16.f32 "
        "{%0,%1,%2,%3}, {%4,%5,%6,%7}, {%8,%9}, {%0,%1,%2,%3};"
        : "+f"(c[0]), "+f"(c[1]), "+f"(c[2]), "+f"(c[3])
        : "r"(a[0]), "r"(a[1]), "r"(a[2]), "r"(a[3]), "r"(b0), "r"(b1));
}
__device__ __forceinline__ void sts_bf16_at(u32 addr, float v) {
    unsigned short b; asm("cvt.rn.bf16.f32 %0, %1;" : "=h"(b) : "f"(v));
    asm volatile("st.shared.b16 [%0], %1;" :: "r"(addr), "h"(b));
}
__device__ __forceinline__ u32 lds_u32(u32 addr) {
    u32 v; asm volatile("ld.shared.b32 %0, [%1];" : "=r"(v) : "r"(addr));
    return v;
}
__device__ __forceinline__ u32 pack_bf16x2(float hi, float lo) {
    u32 p; asm("cvt.rn.bf16x2.f32 %0, %1, %2;" : "=r"(p) : "f"(hi), "f"(lo));
    return p;
}
// group barrier: 4 warps (128 threads), ids 1..4
#define GBAR(id) asm volatile("bar.sync %0, %1;" :: "r"(id), "r"(128) : "memory")

// softplus(100t)/100; 64-entry midpoint LUT, bank-replicated (conflict-free)
__device__ __forceinline__ float sp_lut(float t, const float* lut_lane) {
    float s = fminf(fabsf(t) * 800.0f, 63.0f);
    int i = (int)s;
    return fmaxf(t, 0.f) + 0.01f * lut_lane[i << 5];
}

// ================= pre-pass: tiled transpose (fp32 -> fp16) =================
__global__ void transpose_planes_kernel(const float* __restrict__ planes) {
    __shared__ float t[36*301];
    const int b = blockIdx.x;            // p*300 + y
    const int p = b / GRID_R;
    const int y = b % GRID_R;
    const int tid = threadIdx.x;
    for (int idx = tid; idx < 36*GRID_R; idx += blockDim.x) {
        int c = idx / GRID_R, x = idx % GRID_R;
        t[c*301 + x] = planes[((size_t)(p*NCOMP + c)*GRID_R + y)*GRID_R + x];
    }
    __syncthreads();
    __half* dst = g_planesT + (size_t)(p*GRID_R + y)*GRID_R*NCOMP;
    for (int idx = tid; idx < GRID_R*36; idx += blockDim.x) {
        int x = idx / 36, c = idx % 36;
        dst[idx] = __float2half(t[c*301 + x]);
    }
}

__global__ void prep_weights_kernel(const float* __restrict__ lines,
                                    const float* __restrict__ w1,
                                    const float* __restrict__ b1,
                                    const float* __restrict__ w2) {
    int idx = blockIdx.x*blockDim.x + threadIdx.x;
    if (idx < 3*GRID_R*NCOMP) {
        int c = idx % NCOMP;
        int t = idx / NCOMP;
        int z = t % GRID_R;
        int p = t / GRID_R;
        g_linesT[idx] = lines[(p*NCOMP + c)*GRID_R + z];
    }
    if (idx < 256*144) {
        int k = idx % 144, n = idx / 144;
        float v = (k < IN_CH) ? w1[n*IN_CH + k] : ((k == IN_CH) ? b1[n] : 0.f);
        unsigned short b; asm("cvt.rn.bf16.f32 %0, %1;" : "=h"(b) : "f"(v));
        g_w1bf[idx] = b;
    }
    if (idx < 128*256) {
        float v = w2[idx];
        unsigned short b; asm("cvt.rn.bf16.f32 %0, %1;" : "=h"(b) : "f"(v));
        g_w2bf[idx] = b;
    }
}

// ================= kernel A: gather + embed -> fragment-packed X =================
__global__ __launch_bounds__(GTHREADS)
void gather_kernel(const float* __restrict__ xyz) {
    extern __shared__ __align__(16) char sg[];
    const u32 sa = smem_u32(sg);

    const int tid  = threadIdx.x;
    const int w    = tid >> 5;
    const int lane = tid & 31;
    const int blk  = blockIdx.x;
    const int base = blk * TILE_M;
    const u32 rb   = sa + (u32)w * (16*304);

    // ---- preload this warp's 16 points (48 floats) coalesced, broadcast via shfl ----
    float vA, vB = 0.f;
    {
        const float* xb = xyz + (size_t)(base + w*16)*3;
        vA = xb[lane];
        if (lane < 16) vB = xb[32 + lane];
    }

    #pragma unroll 2
    for (int t = 0; t < 16; t++) {
        const u32 xrow = rb + (u32)t * 304;
        const int i0 = 3*t, i1 = 3*t + 1, i2 = 3*t + 2;
        const float x0 = (i0 < 32) ? __shfl_sync(0xffffffffu, vA, i0) : __shfl_sync(0xffffffffu, vB, i0 - 32);
        const float x1 = (i1 < 32) ? __shfl_sync(0xffffffffu, vA, i1) : __shfl_sync(0xffffffffu, vB, i1 - 32);
        const float x2 = (i2 < 32) ? __shfl_sync(0xffffffffu, vA, i2) : __shfl_sync(0xffffffffu, vB, i2 - 32);

        // embed (lanes 0..20) + bias/pad channels (lanes 0..14)
        if (lane < 21) {
            float v;
            if (lane < 3) v = (lane == 0) ? x0 : ((lane == 1) ? x1 : x2);
            else {
                int tt = lane - 3;
                int iscos = (tt >= 9);
                int q = iscos ? tt - 9 : tt;
                int dim = q / 3, fr = q % 3;
                float xv = (dim == 0) ? x0 : ((dim == 1) ? x1 : x2);
                float ang = xv * (float)(1 << fr);
                v = iscos ? __cosf(ang) : __sinf(ang);
            }
            sts_bf16_at(xrow + lane*2, v);
        }
        if (lane < 15)
            sts_bf16_at(xrow + (129 + lane)*2, (lane == 0) ? 1.0f : 0.f);

        // planes: 54 flat tasks (p = task/18, channel pair pr = task%18), 2 all-lane rounds
        #pragma unroll
        for (int round = 0; round < 2; round++) {
            const int task = round*32 + lane;
            if (task < 54) {
                const int p  = task / 18;
                const int pr = task - p*18;
                float px = (p == 2) ? x1 : x0;
                float py = (p == 0) ? x1 : x2;
                float pz = (p == 0) ? x2 : ((p == 1) ? x1 : x0);
                float fx = (px + 1.f) * 0.5f * (GRID_R - 1);
                float fy = (py + 1.f) * 0.5f * (GRID_R - 1);
                float fz = (pz + 1.f) * 0.5f * (GRID_R - 1);
                int ix = min(max((int)floorf(fx), 0), GRID_R - 2);
                int iy = min(max((int)floorf(fy), 0), GRID_R - 2);
                int iz = min(max((int)floorf(fz), 0), GRID_R - 2);
                float tx = fx - (float)ix, ty = fy - (float)iy, tz = fz - (float)iz;
                float w00 = (1.f - tx) * (1.f - ty);
                float w01 = tx * (1.f - ty);
                float w10 = (1.f - tx) * ty;
                float w11 = tx * ty;
                const __half2* pb2 = (const __half2*)(g_planesT + ((size_t)(p*GRID_R + iy)*GRID_R + ix)*NCOMP);
                float2 a00 = __half22float2(pb2[pr]);
                float2 a01 = __half22float2(pb2[18 + pr]);
                float2 a10 = __half22float2(pb2[(GRID_R*NCOMP)/2 + pr]);
                float2 a11 = __half22float2(pb2[(GRID_R*NCOMP + NCOMP)/2 + pr]);
                float pvx = a00.x*w00 + a01.x*w01 + a10.x*w10 + a11.x*w11;
                float pvy = a00.y*w00 + a01.y*w01 + a10.y*w10 + a11.y*w11;
                const float2* lb2 = (const float2*)(g_linesT + (size_t)(p*GRID_R + iz)*NCOMP);
                float2 l0 = lb2[pr];
                float2 l1 = lb2[18 + pr];
                float lvx = l0.x + tz * (l1.x - l0.x);
                float lvy = l0.y + tz * (l1.y - l0.y);
                const u32 ad = xrow + (u32)(21 + p*36 + 2*pr)*2;
                sts_bf16_at(ad,     pvx * lvx);
                sts_bf16_at(ad + 2, pvy * lvy);
            }
        }
    }
    __syncwarp();

    const int g  = lane >> 2;
    const int tg = lane & 3;
    uint4* dst = g_X + ((size_t)(blk*8 + w)*9)*32 + lane;
    #pragma unroll
    for (int ks = 0; ks < 9; ks++) {
        u32 a0 = lds_u32(rb + (u32)g*304     + ks*32 + tg*4);
        u32 a1 = lds_u32(rb + (u32)(g+8)*304 + ks*32 + tg*4);
        u32 a2 = lds_u32(rb + (u32)g*304     + ks*32 + tg*4 + 16);
        u32 a3 = lds_u32(rb + (u32)(g+8)*304 + ks*32 + tg*4 + 16);
        dst[ks*32] = make_uint4(a0, a1, a2, a3);
    }
}

// ================= kernel B: MLP, 4 independent 4-warp groups =================
__global__ __launch_bounds__(MTHREADS, 1)
void mlp_kernel(const float* __restrict__ w2,
                const float* __restrict__ b2,
                float* __restrict__ out)
{
    extern __shared__ __align__(16) char sm[];
    const u32 sa = smem_u32(sm);

    const int tid  = threadIdx.x;
    const int lane = tid & 31;
    const int grp  = tid >> 7;       // 0..3
    const int gt   = tid & 127;      // thread-in-group
    const int wg   = gt >> 5;        // warp-in-group 0..3
    const int c1   = wg;             // MMA1 cols 64*c1 of 256
    const int c2   = wg;             // MMA2 cols 32*c2 of 128
    const int lg   = lane >> 2;
    const int tg   = lane & 3;
    const int barid = 1 + grp;

    const u32 sa_w1 = sa + W1S_OFF;
    const u32 sa_w2 = sa + W2S_OFF;
    const u32 sa_h  = sa + HS_OFF + (u32)grp * HS_GRP;
    float* lutf  = (float*)(sm + LUT_OFF);
    float* w2c   = (float*)(sm + W2C_OFF);
    float* b2s   = (float*)(sm + B2S_OFF);
    float* c128g = (float*)(sm + C128_OFF) + grp*128;             // [4][32]
    float* stage = (float*)(sm + HS_OFF + grp*HS_GRP);            // overlays H

    for (int idx = tid; idx < 4608; idx += MTHREADS) {
        int n = idx / 18, cc = idx % 18;
        *(uint4*)(sm + W1S_OFF + n*304 + cc*16) = ((const uint4*)g_w1bf)[idx];
    }
    for (int idx = tid; idx < 4096; idx += MTHREADS) {
        int n = idx >> 5, cc = idx & 31;
        *(uint4*)(sm + W2S_OFF + n*528 + cc*16) = ((const uint4*)g_w2bf)[idx];
    }
    for (int i = tid; i < 2048; i += MTHREADS) {
        int e = i >> 5;
        lutf[i] = log1pf(expf(-((float)e + 0.5f) * 0.125f));
    }
    if (tid < 256) w2c[tid] = w2[128*SDF_DIM + tid];
    if (tid < 129) b2s[tid] = b2[tid];
    __syncthreads();

    const float* lut_lane = lutf + lane;

    // per-warp constants (MMA2 epilogue)
    float2 b2v[4];
    #pragma unroll
    for (int nb = 0; nb < 4; nb++) {
        int C = 32*c2 + 8*nb + 2*tg;
        b2v[nb] = make_float2(b2s[C], b2s[C+1]);
    }
    const float b2_128 = b2s[128];

    const int st_row = ((lane >> 3) & 1)*8 + (lane & 7);
    const int st_col = (lane >> 4)*8;

    for (int u = blockIdx.x*4 + grp; u < N_U32; u += gridDim.x*4) {
        const int base = u * 32;

        // ---- MMA1: rows 0..31 of unit, cols 64*c1..+63 ----
        float acc[2][8][4];
        #pragma unroll
        for (int mb = 0; mb < 2; mb++)
            #pragma unroll
            for (int nb = 0; nb < 8; nb++)
                #pragma unroll
                for (int k = 0; k < 4; k++) acc[mb][nb][k] = 0.f;

        const uint4* asrc0 = g_X + ((size_t)(u*2    )*9)*32 + lane;
        const uint4* asrc1 = g_X + ((size_t)(u*2 + 1)*9)*32 + lane;
        const u32 bn0 = 64*c1 + (lane & 7) + ((lane >> 4) & 1)*8;

        uint4 af0 = asrc0[0];
        uint4 af1 = asrc1[0];
        #pragma unroll
        for (int ks = 0; ks < 9; ks++) {
            uint4 nf0, nf1;
            if (ks < 8) { nf0 = asrc0[(ks+1)*32]; nf1 = asrc1[(ks+1)*32]; }
            const u32 bk = ks*32 + ((lane >> 3) & 1)*16;
            #pragma unroll
            for (int q = 0; q < 4; q++) {
                u32 b[4];
                ldsm4(b, sa_w1 + (bn0 + 16*q)*304 + bk);
                mma16816(acc[0][2*q],   (const u32*)&af0, b[0], b[1]);
                mma16816(acc[1][2*q],   (const u32*)&af1, b[0], b[1]);
                mma16816(acc[0][2*q+1], (const u32*)&af0, b[2], b[3]);
                mma16816(acc[1][2*q+1], (const u32*)&af1, b[2], b[3]);
            }
            af0 = nf0; af1 = nf1;
        }

        // ---- softplus + H store via stmatrix + col128 partials ----
        {
            float s128[2][2] = {{0.f,0.f},{0.f,0.f}};
            #pragma unroll
            for (int mb = 0; mb < 2; mb++) {
                const u32 rowbase = sa_h + (u32)(16*mb + st_row)*528;
                #pragma unroll
                for (int nbp = 0; nbp < 4; nbp++) {
                    const int nb0 = 2*nbp;
                    float* d0 = acc[mb][nb0];
                    float* d1 = acc[mb][nb0+1];
                    float h00 = sp_lut(d0[0], lut_lane);
                    float h01 = sp_lut(d0[1], lut_lane);
                    float h02 = sp_lut(d0[2], lut_lane);
                    float h03 = sp_lut(d0[3], lut_lane);
                    float h10 = sp_lut(d1[0], lut_lane);
                    float h11 = sp_lut(d1[1], lut_lane);
                    float h12 = sp_lut(d1[2], lut_lane);
                    float h13 = sp_lut(d1[3], lut_lane);
                    const int C0 = 64*c1 + 8*nb0 + 2*tg;
                    float wc00 = w2c[C0],   wc01 = w2c[C0+1];
                    float wc10 = w2c[C0+8], wc11 = w2c[C0+9];
                    s128[mb][0] = fmaf(h00, wc00, fmaf(h01, wc01, s128[mb][0]));
                    s128[mb][1] = fmaf(h02, wc00, fmaf(h03, wc01, s128[mb][1]));
                    s128[mb][0] = fmaf(h10, wc10, fmaf(h11, wc11, s128[mb][0]));
                    s128[mb][1] = fmaf(h12, wc10, fmaf(h13, wc11, s128[mb][1]));
                    u32 p0 = pack_bf16x2(h01, h00);
                    u32 p1 = pack_bf16x2(h03, h02);
                    u32 p2 = pack_bf16x2(h11, h10);
                    u32 p3 = pack_bf16x2(h13, h12);
                    stsm4(rowbase + (u32)(64*c1 + 8*nb0 + st_col)*2, p0, p1, p2, p3);
                }
            }
            #pragma unroll
            for (int mb = 0; mb < 2; mb++)
                #pragma unroll
                for (int hh = 0; hh < 2; hh++) {
                    float v = s128[mb][hh];
                    v += __shfl_xor_sync(0xffffffffu, v, 1);
                    v += __shfl_xor_sync(0xffffffffu, v, 2);
                    s128[mb][hh] = v;
                }
            if (tg == 0) {
                float* dst = c128g + c1*32;
                #pragma unroll
                for (int mb = 0; mb < 2; mb++) {
                    dst[16*mb + lg]     = s128[mb][0];
                    dst[16*mb + lg + 8] = s128[mb][1];
                }
            }
        }
        GBAR(barid);   // H + c128 visible within group

        // ---- MMA2: rows 0..31, cols 32*c2..+31 ----
        float acc2[2][4][4];
        #pragma unroll
        for (int mb = 0; mb < 2; mb++)
            #pragma unroll
            for (int nb = 0; nb < 4; nb++)
                #pragma unroll
                for (int k = 0; k < 4; k++) acc2[mb][nb][k] = 0.f;

        const u32 bn0b = 32*c2 + (lane & 7) + ((lane >> 4) & 1)*8;
        #pragma unroll 4
        for (int ks = 0; ks < 16; ks++) {
            u32 a0[4], a1[4];
            const u32 abase = sa_h + (u32)(lane & 15)*528 + ks*32 + (lane >> 4)*16;
            ldsm4(a0, abase);
            ldsm4(a1, abase + 16*528);
            const u32 bk = ks*32 + ((lane >> 3) & 1)*16;
            #pragma unroll
            for (int q = 0; q < 2; q++) {
                u32 b[4];
                ldsm4(b, sa_w2 + (bn0b + 16*q)*528 + bk);
                mma16816(acc2[0][2*q],   a0, b[0], b[1]);
                mma16816(acc2[1][2*q],   a1, b[0], b[1]);
                mma16816(acc2[0][2*q+1], a0, b[2], b[3]);
                mma16816(acc2[1][2*q+1], a1, b[2], b[3]);
            }
        }
        GBAR(barid);   // group H reads done; region becomes stage

        // ---- stage + coalesced store ----
        #pragma unroll
        for (int mb = 0; mb < 2; mb++) {
            const int R0 = 16*mb + lg;
            #pragma unroll
            for (int nb = 0; nb < 4; nb++) {
                const int C = 32*c2 + 8*nb + 2*tg;
                float* d = acc2[mb][nb];
                *(float2*)(stage + R0*130 + C)     = make_float2(d[0] + b2v[nb].x, d[1] + b2v[nb].y);
                *(float2*)(stage + (R0+8)*130 + C) = make_float2(d[2] + b2v[nb].x, d[3] + b2v[nb].y);
            }
        }
        if (gt < 32) {
            float s = b2_128;
            #pragma unroll
            for (int k = 0; k < 4; k++) s += c128g[k*32 + gt];
            stage[gt*130 + 128] = s;
        }
        GBAR(barid);
        {
            float* op = out + (size_t)base * OUT_CH;
            for (int i = gt; i < 32*OUT_CH; i += 128) {
                int rr = i / OUT_CH;
                int cc = i - rr*OUT_CH;
                op[i] = stage[rr*130 + cc];
            }
        }
        GBAR(barid);   // stage reads done before next unit's H overwrites
    }
}

// ================= launch =================
extern "C" void kernel_launch(void* const* d_in, const int* in_sizes, int n_in,
                              void* d_out, int out_size) {
    const float* xyz    = (const float*)d_in[0];
    const float* planes = (const float*)d_in[1];
    const float* lines  = (const float*)d_in[2];
    const float* w1     = (const float*)d_in[3];
    const float* b1     = (const float*)d_in[4];
    const float* w2     = (const float*)d_in[5];
    const float* b2     = (const float*)d_in[6];
    float* out = (float*)d_out;

    int sms = 148;
    cudaDeviceGetAttribute(&sms, cudaDevAttrMultiProcessorCount, 0);

    transpose_planes_kernel<<<3*GRID_R, 256>>>(planes);
    prep_weights_kernel<<<(256*144 + 255)/256, 256>>>(lines, w1, b1, w2);
    gather_kernel<<<N_TILES, GTHREADS, 8*16*304>>>(xyz);

    cudaFuncSetAttribute(mlp_kernel, cudaFuncAttributeMaxDynamicSharedMemorySize, SMEM_B);
    mlp_kernel<<<sms, MTHREADS, SMEM_B>>>(w2, b2, out);
}